// round 1
// baseline (speedup 1.0000x reference)
#include <cuda_runtime.h>
#include <cuda_bf16.h>
#include <math.h>
#include <stdint.h>

#define N_NODES 100000
#define N_EDGES 1200000
#define NB_SCAN 196   // ceil(100000/512)

// ---------------- scratch (device globals; no allocation allowed) ----------------
__device__ int   g_is64;
__device__ int   g_deg[N_NODES];
__device__ int   g_rowptr[N_NODES + 1];
__device__ int   g_cursor[N_NODES];
__device__ int   g_csr_src[N_EDGES];
__device__ int   g_csr_eid[N_EDGES];
__device__ int   g_bsums[NB_SCAN];
__device__ float g_S[N_NODES * 16];
__device__ float g_y[(size_t)N_NODES * 64];
__device__ float g_base[(size_t)N_NODES * 64];
__device__ float g_h1[(size_t)N_NODES * 64];
__device__ float g_feat[(size_t)N_NODES * 64];
__device__ float g_h3[(size_t)N_NODES * 64];

// ---------------- edge-index dtype detection (int64 vs int32) ----------------
__global__ void k_detect(const unsigned int* __restrict__ w) {
    // If int64: element e occupies words (2e, 2e+1) and all high words are 0
    // (indices are in [0, 100000)). If int32: odd words are random indices.
    int lane = threadIdx.x;                 // 32 threads
    unsigned int v = w[2 * lane + 1];
    unsigned int ballot = __ballot_sync(0xFFFFFFFFu, v != 0u);
    if (lane == 0) g_is64 = (ballot == 0u) ? 1 : 0;
}

__device__ __forceinline__ int ld_idx(const void* ei, long long i) {
    if (g_is64) return (int)((const long long*)ei)[i];
    return ((const int*)ei)[i];
}

// ---------------- CSR construction ----------------
__global__ void k_zero() {
    int i = blockIdx.x * 256 + threadIdx.x;
    if (i < N_NODES) g_deg[i] = 0;
}

__global__ void k_count(const void* __restrict__ ei) {
    int e = blockIdx.x * 256 + threadIdx.x;
    if (e < N_EDGES) {
        int d = ld_idx(ei, (long long)N_EDGES + e);
        atomicAdd(&g_deg[d], 1);
    }
}

__global__ void k_scan1() {
    __shared__ int s[512];
    int i = blockIdx.x * 512 + threadIdx.x;
    int v = (i < N_NODES) ? g_deg[i] : 0;
    s[threadIdx.x] = v;
    __syncthreads();
    #pragma unroll
    for (int off = 1; off < 512; off <<= 1) {
        int t = (threadIdx.x >= off) ? s[threadIdx.x - off] : 0;
        __syncthreads();
        s[threadIdx.x] += t;
        __syncthreads();
    }
    if (i < N_NODES) g_rowptr[i] = s[threadIdx.x];   // inclusive within block
    if (threadIdx.x == 511) g_bsums[blockIdx.x] = s[511];
}

__global__ void k_scan2() {
    if (threadIdx.x == 0 && blockIdx.x == 0) {
        int acc = 0;
        for (int i = 0; i < NB_SCAN; i++) { int t = g_bsums[i]; g_bsums[i] = acc; acc += t; }
    }
}

__global__ void k_scan3() {
    int i = blockIdx.x * 512 + threadIdx.x;
    if (i < N_NODES) {
        int excl = g_rowptr[i] - g_deg[i] + g_bsums[blockIdx.x];
        g_rowptr[i] = excl;
        g_cursor[i] = excl;
    }
    if (i == 0) g_rowptr[N_NODES] = N_EDGES;
}

__global__ void k_fill(const void* __restrict__ ei) {
    int e = blockIdx.x * 256 + threadIdx.x;
    if (e < N_EDGES) {
        int s = ld_idx(ei, e);
        int d = ld_idx(ei, (long long)N_EDGES + e);
        int p = atomicAdd(&g_cursor[d], 1);
        g_csr_src[p] = s;
        g_csr_eid[p] = e;
    }
}

// ---------------- S = segment_sum(edge_attr, dst)  [N,16] ----------------
__global__ void k_S(const float* __restrict__ ea) {
    int tid = threadIdx.x;                       // 256
    int node = blockIdx.x * 16 + (tid >> 4);
    int t = tid & 15;
    if (node >= N_NODES) return;
    int b = g_rowptr[node], e = g_rowptr[node + 1];
    float acc = 0.f;
    for (int i = b; i < e; i++) {
        int eid = g_csr_eid[i];
        acc += ea[(size_t)eid * 16 + t];
    }
    g_S[node * 16 + t] = acc;
}

// ---------------- dual GEMM: y = h@Wm ; base = h@Ws + S@We ----------------
// 128 threads, tile 64 rows x 64 cols; each thread 8 rows x 4 cols x 2 mats.
__global__ __launch_bounds__(128) void k_gemm(
    const float* __restrict__ x, int sel,
    const float* __restrict__ Wm, const float* __restrict__ Ws,
    const float* __restrict__ We, int K)
{
    const float* hin = (sel == 0) ? x : ((sel == 1) ? g_h1 : g_feat);
    __shared__ float sh_h[64 * 33];
    __shared__ float sh_wa[32 * 64];
    __shared__ float sh_wb[32 * 64];

    int tid = threadIdx.x;
    int rg = tid >> 4;          // 0..7  -> rows rg*8 .. rg*8+7
    int cg = tid & 15;          // 0..15 -> cols cg*4 .. cg*4+3
    int c0 = cg * 4;
    int row0 = blockIdx.x * 64;

    float accA[8][4], accB[8][4];
    #pragma unroll
    for (int i = 0; i < 8; i++)
        #pragma unroll
        for (int j = 0; j < 4; j++) { accA[i][j] = 0.f; accB[i][j] = 0.f; }

    for (int kk = 0; kk < K; kk += 32) {
        // stage h tile 64x32 (padded stride 33)
        #pragma unroll
        for (int i = 0; i < 4; i++) {
            int lin = i * 512 + tid * 4;
            int r = lin >> 5, k = lin & 31;
            float4 v = make_float4(0.f, 0.f, 0.f, 0.f);
            int gr = row0 + r;
            if (gr < N_NODES) v = *(const float4*)(hin + (size_t)gr * K + kk + k);
            float* p = &sh_h[r * 33 + k];
            p[0] = v.x; p[1] = v.y; p[2] = v.z; p[3] = v.w;
        }
        // stage weights 32x64 each
        #pragma unroll
        for (int i = 0; i < 4; i++) {
            int lin = i * 512 + tid * 4;
            int k = lin >> 6, c = lin & 63;
            *(float4*)&sh_wa[k * 64 + c] = *(const float4*)(Wm + (size_t)(kk + k) * 64 + c);
            *(float4*)&sh_wb[k * 64 + c] = *(const float4*)(Ws + (size_t)(kk + k) * 64 + c);
        }
        __syncthreads();

        #pragma unroll
        for (int k = 0; k < 32; k++) {
            float hf[8];
            #pragma unroll
            for (int i = 0; i < 8; i++) hf[i] = sh_h[(rg * 8 + i) * 33 + k];
            float4 wa = *(float4*)&sh_wa[k * 64 + c0];
            float4 wb = *(float4*)&sh_wb[k * 64 + c0];
            #pragma unroll
            for (int i = 0; i < 8; i++) {
                accA[i][0] += hf[i] * wa.x; accA[i][1] += hf[i] * wa.y;
                accA[i][2] += hf[i] * wa.z; accA[i][3] += hf[i] * wa.w;
                accB[i][0] += hf[i] * wb.x; accB[i][1] += hf[i] * wb.y;
                accB[i][2] += hf[i] * wb.z; accB[i][3] += hf[i] * wb.w;
            }
        }
        __syncthreads();
    }

    // add S @ We into accB (K=16)
    {
        #pragma unroll
        for (int i = 0; i < 2; i++) {
            int lin = i * 512 + tid * 4;
            int r = lin >> 4, k = lin & 15;
            float4 v = make_float4(0.f, 0.f, 0.f, 0.f);
            int gr = row0 + r;
            if (gr < N_NODES) v = *(const float4*)(g_S + (size_t)gr * 16 + k);
            float* p = &sh_h[r * 17 + k];
            p[0] = v.x; p[1] = v.y; p[2] = v.z; p[3] = v.w;
        }
        #pragma unroll
        for (int i = 0; i < 2; i++) {
            int lin = i * 512 + tid * 4;
            int k = lin >> 6, c = lin & 63;
            *(float4*)&sh_wa[k * 64 + c] = *(const float4*)(We + (size_t)k * 64 + c);
        }
        __syncthreads();
        #pragma unroll
        for (int k = 0; k < 16; k++) {
            float sf[8];
            #pragma unroll
            for (int i = 0; i < 8; i++) sf[i] = sh_h[(rg * 8 + i) * 17 + k];
            float4 we4 = *(float4*)&sh_wa[k * 64 + c0];
            #pragma unroll
            for (int i = 0; i < 8; i++) {
                accB[i][0] += sf[i] * we4.x; accB[i][1] += sf[i] * we4.y;
                accB[i][2] += sf[i] * we4.z; accB[i][3] += sf[i] * we4.w;
            }
        }
    }

    #pragma unroll
    for (int i = 0; i < 8; i++) {
        int gr = row0 + rg * 8 + i;
        if (gr < N_NODES) {
            *(float4*)&g_y[(size_t)gr * 64 + c0]    = make_float4(accA[i][0], accA[i][1], accA[i][2], accA[i][3]);
            *(float4*)&g_base[(size_t)gr * 64 + c0] = make_float4(accB[i][0], accB[i][1], accB[i][2], accB[i][3]);
        }
    }
}

// ---------------- aggregation: h_out = elu(base + bs + deg*(bm+be) + sum_edges y[src]) ----------------
__global__ __launch_bounds__(128) void k_aggr(
    const float* __restrict__ bm, const float* __restrict__ be,
    const float* __restrict__ bs, int outsel)
{
    int tid = threadIdx.x;
    int node = blockIdx.x * 8 + (tid >> 4);
    int t = tid & 15;
    if (node >= N_NODES) return;

    float4 acc = *(const float4*)(g_base + (size_t)node * 64 + t * 4);
    float4 vbs = *(const float4*)(bs + t * 4);
    float4 vbm = *(const float4*)(bm + t * 4);
    float4 vbe = *(const float4*)(be + t * 4);
    float degf = (float)g_deg[node];
    acc.x += vbs.x + degf * (vbm.x + vbe.x);
    acc.y += vbs.y + degf * (vbm.y + vbe.y);
    acc.z += vbs.z + degf * (vbm.z + vbe.z);
    acc.w += vbs.w + degf * (vbm.w + vbe.w);

    int b = g_rowptr[node], e = g_rowptr[node + 1];
    for (int i = b; i < e; i++) {
        int s = g_csr_src[i];
        float4 v = *(const float4*)(g_y + (size_t)s * 64 + t * 4);
        acc.x += v.x; acc.y += v.y; acc.z += v.z; acc.w += v.w;
    }
    // elu
    acc.x = acc.x > 0.f ? acc.x : expm1f(acc.x);
    acc.y = acc.y > 0.f ? acc.y : expm1f(acc.y);
    acc.z = acc.z > 0.f ? acc.z : expm1f(acc.z);
    acc.w = acc.w > 0.f ? acc.w : expm1f(acc.w);

    float* outp = (outsel == 1) ? g_h1 : ((outsel == 2) ? g_feat : g_h3);
    *(float4*)(outp + (size_t)node * 64 + t * 4) = acc;
}

// ---------------- final: logit = h3@Wl + bl ; outputs ----------------
__global__ void k_final(const float* __restrict__ Wl, const float* __restrict__ bl,
                        float* __restrict__ out)
{
    int gw = (blockIdx.x * 256 + threadIdx.x) >> 5;   // global warp = node
    int lane = threadIdx.x & 31;
    if (gw >= N_NODES) return;
    float2 h = *(const float2*)(g_h3 + (size_t)gw * 64 + lane * 2);
    float2 w = *(const float2*)(Wl + lane * 2);
    float p = h.x * w.x + h.y * w.y;
    #pragma unroll
    for (int off = 16; off > 0; off >>= 1) p += __shfl_xor_sync(0xFFFFFFFFu, p, off);
    if (lane == 0) {
        float logit = p + bl[0];
        out[gw] = 1.f / (1.f + expf(-logit));                                   // part0: sigmoid
        out[(size_t)N_NODES + 64 * (size_t)N_NODES + (size_t)gw * 65 + 64] = logit;  // part2 col 64
    }
}

__global__ void k_copy(float* __restrict__ out) {
    int i = blockIdx.x * 256 + threadIdx.x;
    if (i >= N_NODES * 64) return;
    float v = g_feat[i];
    out[(size_t)N_NODES + i] = v;                      // part1: feat [N,64]
    int n = i >> 6, c = i & 63;
    out[(size_t)N_NODES + 64 * (size_t)N_NODES + (size_t)n * 65 + c] = v;  // part2 cols 0..63
}

// ---------------- launch ----------------
extern "C" void kernel_launch(void* const* d_in, const int* in_sizes, int n_in,
                              void* d_out, int out_size)
{
    const float* x   = (const float*)d_in[0];
    const void*  ei  = d_in[1];
    const float* ea  = (const float*)d_in[2];
    const float* Wm1 = (const float*)d_in[3];
    const float* bm1 = (const float*)d_in[4];
    const float* We1 = (const float*)d_in[5];
    const float* be1 = (const float*)d_in[6];
    const float* Ws1 = (const float*)d_in[7];
    const float* bs1 = (const float*)d_in[8];
    const float* Wm2 = (const float*)d_in[9];
    const float* bm2 = (const float*)d_in[10];
    const float* We2 = (const float*)d_in[11];
    const float* be2 = (const float*)d_in[12];
    const float* Ws2 = (const float*)d_in[13];
    const float* bs2 = (const float*)d_in[14];
    const float* Wm3 = (const float*)d_in[15];
    const float* bm3 = (const float*)d_in[16];
    const float* We3 = (const float*)d_in[17];
    const float* be3 = (const float*)d_in[18];
    const float* Ws3 = (const float*)d_in[19];
    const float* bs3 = (const float*)d_in[20];
    const float* Wl  = (const float*)d_in[21];
    const float* bl  = (const float*)d_in[22];
    float* out = (float*)d_out;

    k_detect<<<1, 32>>>((const unsigned int*)ei);
    k_zero<<<(N_NODES + 255) / 256, 256>>>();
    k_count<<<(N_EDGES + 255) / 256, 256>>>(ei);
    k_scan1<<<NB_SCAN, 512>>>();
    k_scan2<<<1, 32>>>();
    k_scan3<<<NB_SCAN, 512>>>();
    k_fill<<<(N_EDGES + 255) / 256, 256>>>(ei);
    k_S<<<(N_NODES + 15) / 16, 256>>>(ea);

    // layer 1 (K=128, input x)
    k_gemm<<<(N_NODES + 63) / 64, 128>>>(x, 0, Wm1, Ws1, We1, 128);
    k_aggr<<<(N_NODES + 7) / 8, 128>>>(bm1, be1, bs1, 1);
    // layer 2 (K=64, input h1) -> feat
    k_gemm<<<(N_NODES + 63) / 64, 128>>>(x, 1, Wm2, Ws2, We2, 64);
    k_aggr<<<(N_NODES + 7) / 8, 128>>>(bm2, be2, bs2, 2);
    // layer 3 (K=64, input feat) -> h3
    k_gemm<<<(N_NODES + 63) / 64, 128>>>(x, 2, Wm3, Ws3, We3, 64);
    k_aggr<<<(N_NODES + 7) / 8, 128>>>(bm3, be3, bs3, 3);

    k_final<<<(N_NODES * 32 + 255) / 256, 256>>>(Wl, bl, out);
    k_copy<<<(N_NODES * 64 + 255) / 256, 256>>>(out);
}

// round 2
// speedup vs baseline: 1.0481x; 1.0481x over previous
#include <cuda_runtime.h>
#include <cuda_bf16.h>
#include <math.h>
#include <stdint.h>

#define N_NODES 100000
#define N_EDGES 1200000
#define NB_SCAN 196   // ceil(100000/512)

typedef unsigned long long u64;

// ---------------- scratch (device globals; no allocation allowed) ----------------
__device__ int   g_is64;
__device__ int   g_deg[N_NODES];
__device__ int   g_rowptr[N_NODES + 1];
__device__ int   g_cursor[N_NODES];
__device__ int   g_csr_src[N_EDGES];
__device__ int   g_csr_eid[N_EDGES];
__device__ int   g_bsums[NB_SCAN];
__device__ float g_S[N_NODES * 16];
__device__ float g_y[(size_t)N_NODES * 64];
__device__ float g_base[(size_t)N_NODES * 64];
__device__ float g_h1[(size_t)N_NODES * 64];
__device__ float g_feat[(size_t)N_NODES * 64];
__device__ float g_h3[(size_t)N_NODES * 64];

// ---------------- f32x2 packed-pair helpers (FFMA2 path, sm_103a) ----------------
__device__ __forceinline__ u64 pack2(float lo, float hi) {
    u64 r;
    asm("mov.b64 %0, {%1, %2};" : "=l"(r) : "f"(lo), "f"(hi));
    return r;
}
__device__ __forceinline__ void unpack2(u64 v, float& lo, float& hi) {
    asm("mov.b64 {%0, %1}, %2;" : "=f"(lo), "=f"(hi) : "l"(v));
}
__device__ __forceinline__ void ffma2(u64& d, u64 a, u64 b) {
    asm("fma.rn.f32x2 %0, %1, %2, %0;" : "+l"(d) : "l"(a), "l"(b));
}

// ---------------- edge-index dtype detection (int64 vs int32) ----------------
__global__ void k_detect(const unsigned int* __restrict__ w) {
    int lane = threadIdx.x;                 // 32 threads
    unsigned int v = w[2 * lane + 1];
    unsigned int ballot = __ballot_sync(0xFFFFFFFFu, v != 0u);
    if (lane == 0) g_is64 = (ballot == 0u) ? 1 : 0;
}

__device__ __forceinline__ int ld_idx(const void* ei, long long i) {
    if (g_is64) return (int)((const long long*)ei)[i];
    return ((const int*)ei)[i];
}

// ---------------- CSR construction ----------------
__global__ void k_zero() {
    int i = blockIdx.x * 256 + threadIdx.x;
    if (i < N_NODES) g_deg[i] = 0;
}

__global__ void k_count(const void* __restrict__ ei) {
    int e = blockIdx.x * 256 + threadIdx.x;
    if (e < N_EDGES) {
        int d = ld_idx(ei, (long long)N_EDGES + e);
        atomicAdd(&g_deg[d], 1);
    }
}

__global__ void k_scan1() {
    __shared__ int s[512];
    int i = blockIdx.x * 512 + threadIdx.x;
    int v = (i < N_NODES) ? g_deg[i] : 0;
    s[threadIdx.x] = v;
    __syncthreads();
    #pragma unroll
    for (int off = 1; off < 512; off <<= 1) {
        int t = (threadIdx.x >= off) ? s[threadIdx.x - off] : 0;
        __syncthreads();
        s[threadIdx.x] += t;
        __syncthreads();
    }
    if (i < N_NODES) g_rowptr[i] = s[threadIdx.x];   // inclusive within block
    if (threadIdx.x == 511) g_bsums[blockIdx.x] = s[511];
}

__global__ void k_scan2() {
    if (threadIdx.x == 0 && blockIdx.x == 0) {
        int acc = 0;
        for (int i = 0; i < NB_SCAN; i++) { int t = g_bsums[i]; g_bsums[i] = acc; acc += t; }
    }
}

__global__ void k_scan3() {
    int i = blockIdx.x * 512 + threadIdx.x;
    if (i < N_NODES) {
        int excl = g_rowptr[i] - g_deg[i] + g_bsums[blockIdx.x];
        g_rowptr[i] = excl;
        g_cursor[i] = excl;
    }
    if (i == 0) g_rowptr[N_NODES] = N_EDGES;
}

__global__ void k_fill(const void* __restrict__ ei) {
    int e = blockIdx.x * 256 + threadIdx.x;
    if (e < N_EDGES) {
        int s = ld_idx(ei, e);
        int d = ld_idx(ei, (long long)N_EDGES + e);
        int p = atomicAdd(&g_cursor[d], 1);
        g_csr_src[p] = s;
        g_csr_eid[p] = e;
    }
}

// ---------------- S = segment_sum(edge_attr, dst)  [N,16] ----------------
__global__ void k_S(const float* __restrict__ ea) {
    int tid = threadIdx.x;                       // 256
    int node = blockIdx.x * 16 + (tid >> 4);
    int t = tid & 15;
    if (node >= N_NODES) return;
    int b = g_rowptr[node], e = g_rowptr[node + 1];
    float acc = 0.f;
    for (int i = b; i < e; i++) {
        int eid = g_csr_eid[i];
        acc += ea[(size_t)eid * 16 + t];
    }
    g_S[node * 16 + t] = acc;
}

// ---------------- dual GEMM: y = h@Wm ; base = h@Ws + S@We ----------------
// 128 threads, tile 64 rows x 64 cols; each thread 8 rows x 4 cols x 2 mats.
// Inner loop uses packed fma.rn.f32x2 (FFMA2): 2 cols per instruction.
__global__ __launch_bounds__(128) void k_gemm(
    const float* __restrict__ x, int sel,
    const float* __restrict__ Wm, const float* __restrict__ Ws,
    const float* __restrict__ We, int K)
{
    const float* hin = (sel == 0) ? x : ((sel == 1) ? g_h1 : g_feat);
    __shared__ __align__(16) float sh_h[64 * 33];
    __shared__ __align__(16) float sh_wa[32 * 64];
    __shared__ __align__(16) float sh_wb[32 * 64];

    int tid = threadIdx.x;
    int rg = tid >> 4;          // 0..7  -> rows rg*8 .. rg*8+7
    int cg = tid & 15;          // 0..15 -> cols cg*4 .. cg*4+3
    int c0 = cg * 4;
    int row0 = blockIdx.x * 64;

    // packed accumulators: [row][col-pair] x 2 matrices
    u64 accA[8][2], accB[8][2];
    #pragma unroll
    for (int i = 0; i < 8; i++) {
        accA[i][0] = pack2(0.f, 0.f); accA[i][1] = pack2(0.f, 0.f);
        accB[i][0] = pack2(0.f, 0.f); accB[i][1] = pack2(0.f, 0.f);
    }

    for (int kk = 0; kk < K; kk += 32) {
        // stage h tile 64x32 (padded stride 33)
        #pragma unroll
        for (int i = 0; i < 4; i++) {
            int lin = i * 512 + tid * 4;
            int r = lin >> 5, k = lin & 31;
            float4 v = make_float4(0.f, 0.f, 0.f, 0.f);
            int gr = row0 + r;
            if (gr < N_NODES) v = *(const float4*)(hin + (size_t)gr * K + kk + k);
            float* p = &sh_h[r * 33 + k];
            p[0] = v.x; p[1] = v.y; p[2] = v.z; p[3] = v.w;
        }
        // stage weights 32x64 each
        #pragma unroll
        for (int i = 0; i < 4; i++) {
            int lin = i * 512 + tid * 4;
            int k = lin >> 6, c = lin & 63;
            *(float4*)&sh_wa[k * 64 + c] = *(const float4*)(Wm + (size_t)(kk + k) * 64 + c);
            *(float4*)&sh_wb[k * 64 + c] = *(const float4*)(Ws + (size_t)(kk + k) * 64 + c);
        }
        __syncthreads();

        #pragma unroll
        for (int k = 0; k < 32; k++) {
            // weight col-pairs straight from smem as 64-bit loads (no packing)
            const u64* pwa = (const u64*)&sh_wa[k * 64 + c0];
            const u64* pwb = (const u64*)&sh_wb[k * 64 + c0];
            u64 wa01 = pwa[0], wa23 = pwa[1];
            u64 wb01 = pwb[0], wb23 = pwb[1];
            #pragma unroll
            for (int i = 0; i < 8; i++) {
                float h = sh_h[(rg * 8 + i) * 33 + k];
                u64 hh = pack2(h, h);
                ffma2(accA[i][0], hh, wa01);
                ffma2(accA[i][1], hh, wa23);
                ffma2(accB[i][0], hh, wb01);
                ffma2(accB[i][1], hh, wb23);
            }
        }
        __syncthreads();
    }

    // add S @ We into accB (K=16)
    {
        #pragma unroll
        for (int i = 0; i < 2; i++) {
            int lin = i * 512 + tid * 4;
            int r = lin >> 4, k = lin & 15;
            float4 v = make_float4(0.f, 0.f, 0.f, 0.f);
            int gr = row0 + r;
            if (gr < N_NODES) v = *(const float4*)(g_S + (size_t)gr * 16 + k);
            float* p = &sh_h[r * 17 + k];
            p[0] = v.x; p[1] = v.y; p[2] = v.z; p[3] = v.w;
        }
        #pragma unroll
        for (int i = 0; i < 2; i++) {
            int lin = i * 512 + tid * 4;
            int k = lin >> 6, c = lin & 63;
            *(float4*)&sh_wa[k * 64 + c] = *(const float4*)(We + (size_t)k * 64 + c);
        }
        __syncthreads();
        #pragma unroll
        for (int k = 0; k < 16; k++) {
            const u64* pwe = (const u64*)&sh_wa[k * 64 + c0];
            u64 we01 = pwe[0], we23 = pwe[1];
            #pragma unroll
            for (int i = 0; i < 8; i++) {
                float s = sh_h[(rg * 8 + i) * 17 + k];
                u64 ss = pack2(s, s);
                ffma2(accB[i][0], ss, we01);
                ffma2(accB[i][1], ss, we23);
            }
        }
    }

    #pragma unroll
    for (int i = 0; i < 8; i++) {
        int gr = row0 + rg * 8 + i;
        if (gr < N_NODES) {
            float4 va, vb;
            unpack2(accA[i][0], va.x, va.y); unpack2(accA[i][1], va.z, va.w);
            unpack2(accB[i][0], vb.x, vb.y); unpack2(accB[i][1], vb.z, vb.w);
            *(float4*)&g_y[(size_t)gr * 64 + c0]    = va;
            *(float4*)&g_base[(size_t)gr * 64 + c0] = vb;
        }
    }
}

// ---------------- aggregation: h_out = elu(base + bs + deg*(bm+be) + sum_edges y[src]) ----------------
__global__ __launch_bounds__(128) void k_aggr(
    const float* __restrict__ bm, const float* __restrict__ be,
    const float* __restrict__ bs, int outsel)
{
    int tid = threadIdx.x;
    int node = blockIdx.x * 8 + (tid >> 4);
    int t = tid & 15;
    if (node >= N_NODES) return;

    float4 acc = *(const float4*)(g_base + (size_t)node * 64 + t * 4);
    float4 vbs = *(const float4*)(bs + t * 4);
    float4 vbm = *(const float4*)(bm + t * 4);
    float4 vbe = *(const float4*)(be + t * 4);
    float degf = (float)g_deg[node];
    acc.x += vbs.x + degf * (vbm.x + vbe.x);
    acc.y += vbs.y + degf * (vbm.y + vbe.y);
    acc.z += vbs.z + degf * (vbm.z + vbe.z);
    acc.w += vbs.w + degf * (vbm.w + vbe.w);

    int b = g_rowptr[node], e = g_rowptr[node + 1];
    for (int i = b; i < e; i++) {
        int s = g_csr_src[i];
        float4 v = *(const float4*)(g_y + (size_t)s * 64 + t * 4);
        acc.x += v.x; acc.y += v.y; acc.z += v.z; acc.w += v.w;
    }
    // elu
    acc.x = acc.x > 0.f ? acc.x : expm1f(acc.x);
    acc.y = acc.y > 0.f ? acc.y : expm1f(acc.y);
    acc.z = acc.z > 0.f ? acc.z : expm1f(acc.z);
    acc.w = acc.w > 0.f ? acc.w : expm1f(acc.w);

    float* outp = (outsel == 1) ? g_h1 : ((outsel == 2) ? g_feat : g_h3);
    *(float4*)(outp + (size_t)node * 64 + t * 4) = acc;
}

// ---------------- final: logit = h3@Wl + bl ; outputs ----------------
__global__ void k_final(const float* __restrict__ Wl, const float* __restrict__ bl,
                        float* __restrict__ out)
{
    int gw = (blockIdx.x * 256 + threadIdx.x) >> 5;   // global warp = node
    int lane = threadIdx.x & 31;
    if (gw >= N_NODES) return;
    float2 h = *(const float2*)(g_h3 + (size_t)gw * 64 + lane * 2);
    float2 w = *(const float2*)(Wl + lane * 2);
    float p = h.x * w.x + h.y * w.y;
    #pragma unroll
    for (int off = 16; off > 0; off >>= 1) p += __shfl_xor_sync(0xFFFFFFFFu, p, off);
    if (lane == 0) {
        float logit = p + bl[0];
        out[gw] = 1.f / (1.f + expf(-logit));                                   // part0: sigmoid
        out[(size_t)N_NODES + 64 * (size_t)N_NODES + (size_t)gw * 65 + 64] = logit;  // part2 col 64
    }
}

__global__ void k_copy(float* __restrict__ out) {
    int i = blockIdx.x * 256 + threadIdx.x;
    if (i >= N_NODES * 64) return;
    float v = g_feat[i];
    out[(size_t)N_NODES + i] = v;                      // part1: feat [N,64]
    int n = i >> 6, c = i & 63;
    out[(size_t)N_NODES + 64 * (size_t)N_NODES + (size_t)n * 65 + c] = v;  // part2 cols 0..63
}

// ---------------- launch ----------------
extern "C" void kernel_launch(void* const* d_in, const int* in_sizes, int n_in,
                              void* d_out, int out_size)
{
    const float* x   = (const float*)d_in[0];
    const void*  ei  = d_in[1];
    const float* ea  = (const float*)d_in[2];
    const float* Wm1 = (const float*)d_in[3];
    const float* bm1 = (const float*)d_in[4];
    const float* We1 = (const float*)d_in[5];
    const float* be1 = (const float*)d_in[6];
    const float* Ws1 = (const float*)d_in[7];
    const float* bs1 = (const float*)d_in[8];
    const float* Wm2 = (const float*)d_in[9];
    const float* bm2 = (const float*)d_in[10];
    const float* We2 = (const float*)d_in[11];
    const float* be2 = (const float*)d_in[12];
    const float* Ws2 = (const float*)d_in[13];
    const float* bs2 = (const float*)d_in[14];
    const float* Wm3 = (const float*)d_in[15];
    const float* bm3 = (const float*)d_in[16];
    const float* We3 = (const float*)d_in[17];
    const float* be3 = (const float*)d_in[18];
    const float* Ws3 = (const float*)d_in[19];
    const float* bs3 = (const float*)d_in[20];
    const float* Wl  = (const float*)d_in[21];
    const float* bl  = (const float*)d_in[22];
    float* out = (float*)d_out;

    k_detect<<<1, 32>>>((const unsigned int*)ei);
    k_zero<<<(N_NODES + 255) / 256, 256>>>();
    k_count<<<(N_EDGES + 255) / 256, 256>>>(ei);
    k_scan1<<<NB_SCAN, 512>>>();
    k_scan2<<<1, 32>>>();
    k_scan3<<<NB_SCAN, 512>>>();
    k_fill<<<(N_EDGES + 255) / 256, 256>>>(ei);
    k_S<<<(N_NODES + 15) / 16, 256>>>(ea);

    // layer 1 (K=128, input x)
    k_gemm<<<(N_NODES + 63) / 64, 128>>>(x, 0, Wm1, Ws1, We1, 128);
    k_aggr<<<(N_NODES + 7) / 8, 128>>>(bm1, be1, bs1, 1);
    // layer 2 (K=64, input h1) -> feat
    k_gemm<<<(N_NODES + 63) / 64, 128>>>(x, 1, Wm2, Ws2, We2, 64);
    k_aggr<<<(N_NODES + 7) / 8, 128>>>(bm2, be2, bs2, 2);
    // layer 3 (K=64, input feat) -> h3
    k_gemm<<<(N_NODES + 63) / 64, 128>>>(x, 2, Wm3, Ws3, We3, 64);
    k_aggr<<<(N_NODES + 7) / 8, 128>>>(bm3, be3, bs3, 3);

    k_final<<<(N_NODES * 32 + 255) / 256, 256>>>(Wl, bl, out);
    k_copy<<<(N_NODES * 64 + 255) / 256, 256>>>(out);
}